// round 3
// baseline (speedup 1.0000x reference)
#include <cuda_runtime.h>
#include <cuda_bf16.h>
#include <math.h>

#define N_NODES 100000
#define N_EDGES 1600000
#define HID 128
#define BN_EPS 1e-5f

// ---------------- device scratch (allocation-free, referenced only from device code) ----------------
__device__ __align__(16) float g_h[(size_t)N_NODES * HID];        // 51.2 MB  (layer activations)
__device__ __align__(16) float g_pq[(size_t)N_NODES * 2 * HID];   // 102.4 MB (p = h@wl | q = h@wr)
__device__ int   g_rowptr[N_NODES + 1];
__device__ int   g_cursor[N_NODES];                 // degree temp, then placement cursor
__device__ int   g_srcs[N_EDGES];

// ---------------- CSR build ----------------
__global__ void k_zero_deg() {
    int i = blockIdx.x * blockDim.x + threadIdx.x;
    if (i < N_NODES) g_cursor[i] = 0;
}

// edge_index is int32 on device: [2, E] row-major. src = ei[e], dst = ei[N_EDGES + e].
__global__ void k_hist(const int* __restrict__ ei) {
    int e = blockIdx.x * blockDim.x + threadIdx.x;
    if (e < N_EDGES) {
        int dst = ei[N_EDGES + e];
        if (dst >= 0 && dst < N_NODES)      // defensive: never fault
            atomicAdd(&g_cursor[dst], 1);
    }
}

// single-block exclusive scan of degrees -> rowptr
__global__ void k_scan() {
    __shared__ int sums[1024];
    const int CH = (N_NODES + 1023) / 1024;   // 98
    int t = threadIdx.x;
    int lo = t * CH;
    int hi = min(lo + CH, N_NODES);
    int s = 0;
    for (int i = lo; i < hi; ++i) s += g_cursor[i];
    sums[t] = s;
    __syncthreads();
    // Hillis-Steele inclusive scan
    for (int off = 1; off < 1024; off <<= 1) {
        int v = (t >= off) ? sums[t - off] : 0;
        __syncthreads();
        sums[t] += v;
        __syncthreads();
    }
    int run = (t == 0) ? 0 : sums[t - 1];
    for (int i = lo; i < hi; ++i) {
        int d = g_cursor[i];
        g_rowptr[i] = run;
        run += d;
    }
    if (t == 1023) g_rowptr[N_NODES] = sums[1023];
}

__global__ void k_cursor_init() {
    int i = blockIdx.x * blockDim.x + threadIdx.x;
    if (i < N_NODES) g_cursor[i] = g_rowptr[i];
}

__global__ void k_place(const int* __restrict__ ei) {
    int e = blockIdx.x * blockDim.x + threadIdx.x;
    if (e < N_EDGES) {
        int src = ei[e];
        int dst = ei[N_EDGES + e];
        if (dst >= 0 && dst < N_NODES && src >= 0 && src < N_NODES) {
            int pos = atomicAdd(&g_cursor[dst], 1);
            if (pos >= 0 && pos < N_EDGES) g_srcs[pos] = src;
        }
    }
}

// ---------------- GEMM: g_pq[:, blockIdx.y*128 : +128] = A @ (blockIdx.y ? wr : wl) ----------------
// A = layer0 ? X (harness input) : g_h.  A: [N_NODES, K] row-major. W: [K, 128] row-major.
__global__ __launch_bounds__(256) void k_gemm(const float* __restrict__ X, int K,
                                              const float* __restrict__ Wl,
                                              const float* __restrict__ Wr,
                                              int layer0) {
    __shared__ float As[16][136];   // transposed tile, padded
    __shared__ float Bs[16][128];

    const float* __restrict__ A = layer0 ? X : (const float*)g_h;
    const int m0 = blockIdx.x * 128;
    const float* __restrict__ B = blockIdx.y ? Wr : Wl;

    int t = threadIdx.x;
    int tx = t & 15;        // 0..15 -> 8 output cols each
    int ty = t >> 4;        // 0..15 -> 8 output rows each
    int ar = t >> 2;        // 0..63 (A load row within tile)
    int ac = (t & 3) * 4;   // 0,4,8,12 (A load k offset)
    int br = t >> 5;        // 0..7  (B load k row)
    int bc = (t & 31) * 4;  // B load col

    float acc[8][8];
#pragma unroll
    for (int i = 0; i < 8; ++i)
#pragma unroll
        for (int j = 0; j < 8; ++j) acc[i][j] = 0.f;

    for (int k0 = 0; k0 < K; k0 += 16) {
        // load A tile (128 x 16), store transposed
#pragma unroll
        for (int half = 0; half < 2; ++half) {
            int row = m0 + ar + half * 64;
            float4 v = make_float4(0.f, 0.f, 0.f, 0.f);
            if (row < N_NODES)
                v = *(const float4*)(A + (size_t)row * K + k0 + ac);
            As[ac + 0][ar + half * 64] = v.x;
            As[ac + 1][ar + half * 64] = v.y;
            As[ac + 2][ar + half * 64] = v.z;
            As[ac + 3][ar + half * 64] = v.w;
        }
        // load B tile (16 x 128)
#pragma unroll
        for (int half = 0; half < 2; ++half) {
            int kk = k0 + br + half * 8;
            float4 v = *(const float4*)(B + (size_t)kk * 128 + bc);
            *(float4*)&Bs[br + half * 8][bc] = v;
        }
        __syncthreads();

#pragma unroll
        for (int k = 0; k < 16; ++k) {
            float a[8], b[8];
            *(float4*)(a)     = *(const float4*)&As[k][ty * 8];
            *(float4*)(a + 4) = *(const float4*)&As[k][ty * 8 + 4];
            *(float4*)(b)     = *(const float4*)&Bs[k][tx * 8];
            *(float4*)(b + 4) = *(const float4*)&Bs[k][tx * 8 + 4];
#pragma unroll
            for (int i = 0; i < 8; ++i)
#pragma unroll
                for (int j = 0; j < 8; ++j)
                    acc[i][j] = fmaf(a[i], b[j], acc[i][j]);
        }
        __syncthreads();
    }

    int colbase = blockIdx.y * 128 + tx * 8;
#pragma unroll
    for (int i = 0; i < 8; ++i) {
        int row = m0 + ty * 8 + i;
        if (row < N_NODES) {
            float* o = g_pq + (size_t)row * 256 + colbase;
            *(float4*)(o)     = *(float4*)&acc[i][0];
            *(float4*)(o + 4) = *(float4*)&acc[i][4];
        }
    }
}

// ---------------- fused aggregation + bias + BN + ReLU ----------------
// g_h[i] = relu( BN( mean_{e: dst=i} p[src_e] + q[i] + bl ) ),   p|q = g_pq
__global__ __launch_bounds__(256) void k_agg(const float* __restrict__ bl,
                                             const float* __restrict__ gam,
                                             const float* __restrict__ bet,
                                             const float* __restrict__ rm,
                                             const float* __restrict__ rv) {
    int node = (blockIdx.x * blockDim.x + threadIdx.x) >> 5;
    if (node >= N_NODES) return;
    int lane = threadIdx.x & 31;
    int c = lane * 4;

    int s0 = g_rowptr[node];
    int s1 = g_rowptr[node + 1];
    float4 acc = make_float4(0.f, 0.f, 0.f, 0.f);
    for (int e = s0; e < s1; ++e) {
        int s = g_srcs[e];
        float4 v = *(const float4*)(g_pq + (size_t)s * 256 + c);
        acc.x += v.x; acc.y += v.y; acc.z += v.z; acc.w += v.w;
    }
    float inv = 1.f / (float)max(s1 - s0, 1);

    float4 q = *(const float4*)(g_pq + (size_t)node * 256 + 128 + c);
    float4 vb  = *(const float4*)(bl + c);
    float4 vg  = *(const float4*)(gam + c);
    float4 vbe = *(const float4*)(bet + c);
    float4 vrm = *(const float4*)(rm + c);
    float4 vrv = *(const float4*)(rv + c);

    float o0 = acc.x * inv + q.x + vb.x;
    float o1 = acc.y * inv + q.y + vb.y;
    float o2 = acc.z * inv + q.z + vb.z;
    float o3 = acc.w * inv + q.w + vb.w;

    o0 = (o0 - vrm.x) * (vg.x * rsqrtf(vrv.x + BN_EPS)) + vbe.x;
    o1 = (o1 - vrm.y) * (vg.y * rsqrtf(vrv.y + BN_EPS)) + vbe.y;
    o2 = (o2 - vrm.z) * (vg.z * rsqrtf(vrv.z + BN_EPS)) + vbe.z;
    o3 = (o3 - vrm.w) * (vg.w * rsqrtf(vrv.w + BN_EPS)) + vbe.w;

    float4 r;
    r.x = fmaxf(o0, 0.f);
    r.y = fmaxf(o1, 0.f);
    r.z = fmaxf(o2, 0.f);
    r.w = fmaxf(o3, 0.f);
    *(float4*)(g_h + (size_t)node * HID + c) = r;
}

// ---------------- final linear head: out[i] = g_h[i] . w + b ----------------
__global__ __launch_bounds__(256) void k_final(const float* __restrict__ w,
                                               const float* __restrict__ b,
                                               float* __restrict__ out) {
    int node = (blockIdx.x * blockDim.x + threadIdx.x) >> 5;
    if (node >= N_NODES) return;
    int lane = threadIdx.x & 31;
    int c = lane * 4;
    float4 hv = *(const float4*)(g_h + (size_t)node * HID + c);
    float4 wv = *(const float4*)(w + c);
    float s = hv.x * wv.x + hv.y * wv.y + hv.z * wv.z + hv.w * wv.w;
#pragma unroll
    for (int off = 16; off > 0; off >>= 1)
        s += __shfl_down_sync(0xffffffffu, s, off);
    if (lane == 0) out[node] = s + b[0];
}

// ---------------- launch ----------------
extern "C" void kernel_launch(void* const* d_in, const int* in_sizes, int n_in,
                              void* d_out, int out_size) {
    const float* x  = (const float*)d_in[0];
    const int*   ei = (const int*)d_in[1];          // int64 in reference -> int32 on device
    // per-layer params at 2 + 7*i : wl, wr, bl, g, be, rm, rv
    const float* wl[3]; const float* wr[3]; const float* bl[3];
    const float* gm[3]; const float* be[3]; const float* rm[3]; const float* rv[3];
    for (int i = 0; i < 3; ++i) {
        const int base = 2 + 7 * i;
        wl[i] = (const float*)d_in[base + 0];
        wr[i] = (const float*)d_in[base + 1];
        bl[i] = (const float*)d_in[base + 2];
        gm[i] = (const float*)d_in[base + 3];
        be[i] = (const float*)d_in[base + 4];
        rm[i] = (const float*)d_in[base + 5];
        rv[i] = (const float*)d_in[base + 6];
    }
    const float* lin_w = (const float*)d_in[23];
    const float* lin_b = (const float*)d_in[24];
    float* out = (float*)d_out;

    const int TB = 256;
    const int nb_nodes = (N_NODES + TB - 1) / TB;
    const int nb_edges = (N_EDGES + TB - 1) / TB;
    const int nb_warps = (N_NODES * 32 + TB - 1) / TB;

    // CSR build (per launch; graph-capturable)
    k_zero_deg<<<nb_nodes, TB>>>();
    k_hist<<<nb_edges, TB>>>(ei);
    k_scan<<<1, 1024>>>();
    k_cursor_init<<<nb_nodes, TB>>>();
    k_place<<<nb_edges, TB>>>(ei);

    // 3 SAGE layers
    dim3 ggrid((N_NODES + 127) / 128, 2);
    // layer 0: A = x, K = 160
    k_gemm<<<ggrid, 256>>>(x, 160, wl[0], wr[0], 1);
    k_agg<<<nb_warps, TB>>>(bl[0], gm[0], be[0], rm[0], rv[0]);
    // layer 1
    k_gemm<<<ggrid, 256>>>(x, 128, wl[1], wr[1], 0);
    k_agg<<<nb_warps, TB>>>(bl[1], gm[1], be[1], rm[1], rv[1]);
    // layer 2
    k_gemm<<<ggrid, 256>>>(x, 128, wl[2], wr[2], 0);
    k_agg<<<nb_warps, TB>>>(bl[2], gm[2], be[2], rm[2], rv[2]);

    // final head
    k_final<<<nb_warps, TB>>>(lin_w, lin_b, out);
}